// round 10
// baseline (speedup 1.0000x reference)
#include <cuda_runtime.h>
#include <cuda_fp16.h>
#include <math.h>
#include <stdint.h>

// Problem constants
#define BB 2
#define SS 2048
#define DM 512
#define HH 8
#define DH 64
#define CH 64               // chunk length
#define NC (SS/CH)          // 32 chunks
#define BH (BB*HH)          // 16 (b,h) pairs

// Scratch (device globals)
__device__ __half g_qh  [BH*SS*DH];     // elu+1, fp16
__device__ __half g_kh  [BH*SS*DH];
__device__ __half g_vh  [BH*SS*DH];
__device__ __half g_ckvh[BH*NC*DH*DH];  // per-chunk (V^T K): [d][e]
__device__ float  g_cks [BH*NC*DH];
__device__ __half g_pkvh[BH*NC*DH*DH];  // exclusive prefix (still [d][e])
__device__ float  g_pks [BH*NC*DH];
__device__ __half g_ctxh[BB*SS*DM];     // context fp16
__device__ __half g_xh  [BB*SS*DM];     // x fp16
__device__ __half g_wh  [3*DM*DM];      // [Wqk ; Wv] fp16
__device__ __half g_woh [DM*DM];        // Wo fp16

// ===========================================================================
// helpers
// ===========================================================================
__device__ __forceinline__ uint32_t smem_u32(const void* p) {
    uint32_t a;
    asm("{ .reg .u64 t; cvta.to.shared.u64 t, %1; cvt.u32.u64 %0, t; }"
        : "=r"(a) : "l"(p));
    return a;
}
__device__ __forceinline__ void ldsm_x4(uint32_t& r0, uint32_t& r1,
                                        uint32_t& r2, uint32_t& r3, uint32_t a) {
    asm volatile("ldmatrix.sync.aligned.m8n8.x4.shared.b16 {%0,%1,%2,%3}, [%4];"
                 : "=r"(r0), "=r"(r1), "=r"(r2), "=r"(r3) : "r"(a));
}
__device__ __forceinline__ void ldsm_x2(uint32_t& r0, uint32_t& r1, uint32_t a) {
    asm volatile("ldmatrix.sync.aligned.m8n8.x2.shared.b16 {%0,%1}, [%2];"
                 : "=r"(r0), "=r"(r1) : "r"(a));
}
__device__ __forceinline__ void mma_f16(float& c0, float& c1, float& c2, float& c3,
                                        uint32_t a0, uint32_t a1, uint32_t a2, uint32_t a3,
                                        uint32_t b0, uint32_t b1) {
    asm volatile("mma.sync.aligned.m16n8k16.row.col.f32.f16.f16.f32 "
                 "{%0,%1,%2,%3}, {%4,%5,%6,%7}, {%8,%9}, {%0,%1,%2,%3};"
                 : "+f"(c0), "+f"(c1), "+f"(c2), "+f"(c3)
                 : "r"(a0), "r"(a1), "r"(a2), "r"(a3), "r"(b0), "r"(b1));
}
#define CP16(dst, src) \
    asm volatile("cp.async.cg.shared.global [%0], [%1], 16;" \
                 :: "r"(dst), "l"(src) : "memory")
#define CP_COMMIT() asm volatile("cp.async.commit_group;" ::: "memory")
#define CP_WAIT2()  asm volatile("cp.async.wait_group 2;" ::: "memory")

// ===========================================================================
// Kernel 0: convert inputs to fp16.
// ===========================================================================
__global__ __launch_bounds__(256) void round_kernel(
    const float* __restrict__ x, const float* __restrict__ Wqk,
    const float* __restrict__ Wv, const float* __restrict__ Wo)
{
    const int tid = blockIdx.x * 256 + threadIdx.x;
    const int stride = gridDim.x * 256;
    const float2* x2 = (const float2*)x;
    __half2* xo = (__half2*)g_xh;
    for (int i = tid; i < BB*SS*DM/2; i += stride) xo[i] = __float22half2_rn(x2[i]);
    const float2* a2 = (const float2*)Wqk;
    __half2* ao = (__half2*)g_wh;
    for (int i = tid; i < 2*DM*DM/2; i += stride) ao[i] = __float22half2_rn(a2[i]);
    const float2* b2 = (const float2*)Wv;
    __half2* bo = (__half2*)(g_wh + 2*DM*DM);
    for (int i = tid; i < DM*DM/2; i += stride) bo[i] = __float22half2_rn(b2[i]);
    const float2* c2 = (const float2*)Wo;
    __half2* co = (__half2*)g_woh;
    for (int i = tid; i < DM*DM/2; i += stride) co[i] = __float22half2_rn(c2[i]);
}

// ===========================================================================
// fp16 mma.sync GEMM, cp.async 4-stage pipeline.
// Tile: 128(M) x 64(N), K=512, BK=32 halves. 128 threads = 4 warps (2M x 2N),
// warp tile 64x32, frags m16n8k16. smem row = 32 halves + 8 pad = 80 B.
// occ 3/SM (smem 60KB) -> proj grid 768 CTAs, 86% last-wave utilization.
// MODE 0: proj (A=g_xh, B=g_wh, bias+elu, scatter q/k/v fp16)
// MODE 1: out  (A=g_ctxh, B=g_woh, bias, store fp32 out)
// ===========================================================================
#define BKH 32
#define ROWB 80
#define TILEA (128*ROWB)                   // 10240
#define TILEBB (64*ROWB)                   // 5120
#define STAGEBH (TILEA+TILEBB)             // 15360
#define NST 4
#define GEMM_SMEM_BYTES (NST*STAGEBH)      // 61440

template<int MODE>
__global__ __launch_bounds__(128, 3) void gemm_f16(
    const float* __restrict__ bias0, const float* __restrict__ bias1,
    float* __restrict__ outp)
{
    extern __shared__ __align__(16) char smem[];
    const int tid = threadIdx.x;
    const int wid = tid >> 5, lane = tid & 31;
    const int wm = wid & 1, wn = wid >> 1;          // 2 x 2 warp grid
    const int jt = blockIdx.x * 64;
    const int nt = blockIdx.y * 128;

    const __half* Ap = (MODE == 1) ? (const __half*)g_ctxh : (const __half*)g_xh;
    const __half* Bp = (MODE == 1) ? (const __half*)g_woh  : (const __half*)g_wh;

    const uint32_t sb = smem_u32(smem);

    // per-thread loads per stage: A 4 x 16B (512 chunks), B 2 x 16B (256 chunks)
    const __half* rowA[4]; uint32_t dA[4];
    const __half* rowB[2]; uint32_t dB[2];
#pragma unroll
    for (int u = 0; u < 4; u++) {
        int idx = tid + u * 128;            // 0..511
        int r = idx >> 2, c = idx & 3;
        dA[u] = (uint32_t)(r * ROWB + c * 16);
        rowA[u] = Ap + (size_t)(nt + r) * DM + c * 8;
    }
#pragma unroll
    for (int u = 0; u < 2; u++) {
        int idx = tid + u * 128;            // 0..255
        int r = idx >> 2, c = idx & 3;
        dB[u] = (uint32_t)(TILEA + r * ROWB + c * 16);
        rowB[u] = Bp + (size_t)(jt + r) * DM + c * 8;
    }

    const uint32_t aoff = (uint32_t)((lane & 15) * ROWB + (lane >> 4) * 16
                                     + wm * 64 * ROWB);
    const uint32_t boff = (uint32_t)((lane & 7) * ROWB + ((lane >> 3) & 1) * 16
                                     + wn * 32 * ROWB) + TILEA;

    float acc[4][4][4] = {};

#pragma unroll
    for (int s = 0; s < 3; s++) {
        const uint32_t st = sb + s * STAGEBH;
        const int k0 = s * BKH;
#pragma unroll
        for (int u = 0; u < 4; u++) CP16(st + dA[u], rowA[u] + k0);
#pragma unroll
        for (int u = 0; u < 2; u++) CP16(st + dB[u], rowB[u] + k0);
        CP_COMMIT();
    }

    for (int it = 0; it < 16; it++) {
        const int buf = it & 3;
        CP_WAIT2();
        __syncthreads();
        const uint32_t abase = sb + buf * STAGEBH + aoff;
        const uint32_t bbase = sb + buf * STAGEBH + boff;
#pragma unroll
        for (int kk = 0; kk < 2; kk++) {
            uint32_t afr[4][4], bfr[4][2];
#pragma unroll
            for (int mf = 0; mf < 4; mf++)
                ldsm_x4(afr[mf][0], afr[mf][1], afr[mf][2], afr[mf][3],
                        abase + (uint32_t)(mf * 16 * ROWB) + kk * 32);
#pragma unroll
            for (int nf = 0; nf < 4; nf++)
                ldsm_x2(bfr[nf][0], bfr[nf][1],
                        bbase + (uint32_t)(nf * 8 * ROWB) + kk * 32);
#pragma unroll
            for (int mf = 0; mf < 4; mf++)
#pragma unroll
                for (int nf = 0; nf < 4; nf++)
                    mma_f16(acc[mf][nf][0], acc[mf][nf][1],
                            acc[mf][nf][2], acc[mf][nf][3],
                            afr[mf][0], afr[mf][1], afr[mf][2], afr[mf][3],
                            bfr[nf][0], bfr[nf][1]);
        }
        __syncthreads();
        const int nxt = it + 3;
        if (nxt < 16) {
            const uint32_t st = sb + (nxt & 3) * STAGEBH;
            const int k0 = nxt * BKH;
#pragma unroll
            for (int u = 0; u < 4; u++) CP16(st + dA[u], rowA[u] + k0);
#pragma unroll
            for (int u = 0; u < 2; u++) CP16(st + dB[u], rowB[u] + k0);
        }
        CP_COMMIT();
    }

    const int rl = lane >> 2, cl = (lane & 3) * 2;
#pragma unroll
    for (int mf = 0; mf < 4; mf++) {
#pragma unroll
        for (int nf = 0; nf < 4; nf++) {
            const int j0 = jt + wn * 32 + nf * 8 + cl;
#pragma unroll
            for (int half = 0; half < 2; half++) {
                const int row = nt + wm * 64 + mf * 16 + rl + half * 8;
                float v0 = acc[mf][nf][half * 2 + 0];
                float v1 = acc[mf][nf][half * 2 + 1];
                if (MODE == 0) {
                    const int b_ = row >> 11, s_ = row & (SS - 1);
                    if (j0 < 2 * DM) {
                        v0 += bias0[j0]; v1 += bias0[j0 + 1];
                        v0 = (v0 > 0.f) ? v0 + 1.f : expf(v0);
                        v1 = (v1 > 0.f) ? v1 + 1.f : expf(v1);
                        int jm = j0 & (DM - 1);
                        int h = jm >> 6, d = jm & 63;
                        __half* dst = (j0 < DM ? g_qh : g_kh)
                                    + (((size_t)(b_ * HH + h) * SS + s_) * DH + d);
                        *(__half2*)dst = __floats2half2_rn(v0, v1);
                    } else {
                        int jm = j0 - 2 * DM;
                        v0 += bias1[jm]; v1 += bias1[jm + 1];
                        int h = jm >> 6, d = jm & 63;
                        __half* dst = g_vh + (((size_t)(b_ * HH + h) * SS + s_) * DH + d);
                        *(__half2*)dst = __floats2half2_rn(v0, v1);
                    }
                } else {
                    float2 bi = *(const float2*)(bias0 + j0);
                    *(float2*)(outp + (size_t)row * DM + j0) =
                        make_float2(v0 + bi.x, v1 + bi.y);
                }
            }
        }
    }
}

// ===========================================================================
// Kernel 2: per-chunk M[d][e] = sum_s v[s][d] k[s][e]  (A=v^T, B=k^T), fp16.
// 256 threads = 8 warps (2x4), warp tile 32x16, K=s=64 -> 4 k16 steps.
// Tile rows: 64 halves + 8 pad = 144 B.
// ===========================================================================
#define TPH 72
#define TPHB 144

__global__ __launch_bounds__(256) void chunkkv_kernel()
{
    __shared__ __half sKT[64*TPH];
    __shared__ __half sVT[64*TPH];
    const int c  = blockIdx.x, bh = blockIdx.y;
    const int tid = threadIdx.x;
    const int wid = tid >> 5, lane = tid & 31;
    const int wm = wid & 1, wn = wid >> 1;     // 2 x 4
    const __half* kp = g_kh + ((size_t)bh*SS + (size_t)c*CH)*DH;
    const __half* vp = g_vh + ((size_t)bh*SS + (size_t)c*CH)*DH;

    for (int idx = tid; idx < 2048; idx += 256) {
        int r = idx >> 5, c2 = idx & 31;
        __half2 k2 = *(const __half2*)(kp + r*DH + 2*c2);
        sKT[(2*c2+0)*TPH + r] = __low2half(k2);
        sKT[(2*c2+1)*TPH + r] = __high2half(k2);
        __half2 v2 = *(const __half2*)(vp + r*DH + 2*c2);
        sVT[(2*c2+0)*TPH + r] = __low2half(v2);
        sVT[(2*c2+1)*TPH + r] = __high2half(v2);
    }
    __syncthreads();

    const uint32_t aoff = (uint32_t)((lane & 15) * TPHB + (lane >> 4) * 16);
    const uint32_t boff = (uint32_t)((lane & 7) * TPHB + ((lane >> 3) & 1) * 16);
    const uint32_t abase = smem_u32(sVT) + (uint32_t)(wm * 32 * TPHB) + aoff;
    const uint32_t bbase = smem_u32(sKT) + (uint32_t)(wn * 16 * TPHB) + boff;

    float acc[2][2][4] = {};
#pragma unroll
    for (int kk = 0; kk < 4; kk++) {
        uint32_t afr[2][4], bfr[2][2];
#pragma unroll
        for (int mf = 0; mf < 2; mf++)
            ldsm_x4(afr[mf][0], afr[mf][1], afr[mf][2], afr[mf][3],
                    abase + (uint32_t)(mf * 16 * TPHB) + kk * 32);
#pragma unroll
        for (int nf = 0; nf < 2; nf++)
            ldsm_x2(bfr[nf][0], bfr[nf][1],
                    bbase + (uint32_t)(nf * 8 * TPHB) + kk * 32);
#pragma unroll
        for (int mf = 0; mf < 2; mf++)
#pragma unroll
            for (int nf = 0; nf < 2; nf++)
                mma_f16(acc[mf][nf][0], acc[mf][nf][1],
                        acc[mf][nf][2], acc[mf][nf][3],
                        afr[mf][0], afr[mf][1], afr[mf][2], afr[mf][3],
                        bfr[nf][0], bfr[nf][1]);
    }

    __half* dst = g_ckvh + ((size_t)bh*NC + c)*DH*DH;
    const int rl = lane >> 2, cl = (lane & 3) * 2;
#pragma unroll
    for (int mf = 0; mf < 2; mf++)
#pragma unroll
        for (int nf = 0; nf < 2; nf++)
#pragma unroll
            for (int half = 0; half < 2; half++) {
                int row = wm*32 + mf*16 + rl + half*8;   // d
                int col = wn*16 + nf*8 + cl;             // e
                *(__half2*)(dst + row*DH + col) =
                    __floats2half2_rn(acc[mf][nf][half*2], acc[mf][nf][half*2+1]);
            }

    if (tid < DH) {
        float s = 0.f;
#pragma unroll 8
        for (int r = 0; r < CH; r++) s += __half2float(sKT[tid*TPH + r]);
        g_cks[((size_t)bh*NC + c)*DH + tid] = s;
    }
}

// ===========================================================================
// Kernel 3: exclusive prefix scan, __half2-wide. grid (BH, 8) x 256.
// ===========================================================================
__global__ __launch_bounds__(256) void scan_kernel()
{
    const int bh = blockIdx.x;
    const int tid = threadIdx.x;
    const int e2 = blockIdx.y * 256 + tid;      // 0..2047 (half2 index)
    const size_t base = (size_t)bh * NC;
    const __half2* src = (const __half2*)g_ckvh;
    __half2* dst = (__half2*)g_pkvh;
    __half2 v[NC];
#pragma unroll
    for (int c = 0; c < NC; c++)
        v[c] = src[(base + c) * (DH*DH/2) + e2];
    float rx = 0.f, ry = 0.f;
#pragma unroll
    for (int c = 0; c < NC; c++) {
        dst[(base + c) * (DH*DH/2) + e2] = __floats2half2_rn(rx, ry);
        float2 f = __half22float2(v[c]);
        rx += f.x; ry += f.y;
    }
    if (blockIdx.y == 0 && tid < DH) {
        float w[NC];
#pragma unroll
        for (int c = 0; c < NC; c++) w[c] = g_cks[(base + c)*DH + tid];
        float r = 0.f;
#pragma unroll
        for (int c = 0; c < NC; c++) {
            g_pks[(base + c)*DH + tid] = r;
            r += w[c];
        }
    }
}

// ===========================================================================
// Kernel 4: per-chunk context, fp16 mma, 256 threads = 8 warps (2x4),
// warp tile 32x16.
//  S = q k^T (mask) ; den = rowsum(S_h) + q.ks_pre
//  ctx = (S_h @ v + q @ KV_pre) / den
// ===========================================================================
__global__ __launch_bounds__(256) void ctx_kernel()
{
    __shared__ __half sQ  [64*TPH];   // [t][e]
    __shared__ __half sK  [64*TPH];   // [s][e]
    __shared__ __half sS  [64*TPH];   // [t][s] masked fp16
    __shared__ __half sVT [64*TPH];   // [d][s]
    __shared__ __half sKVT[64*TPH];   // [d][e]
    __shared__ float  sKs [64];
    __shared__ float  sDen[64];

    const int c  = blockIdx.x, bh = blockIdx.y;
    const int tid = threadIdx.x;
    const int wid = tid >> 5, lane = tid & 31;
    const int wm = wid & 1, wn = wid >> 1;     // 2 x 4

    const __half* qp  = g_qh   + ((size_t)bh*SS + (size_t)c*CH)*DH;
    const __half* kp  = g_kh   + ((size_t)bh*SS + (size_t)c*CH)*DH;
    const __half* vp  = g_vh   + ((size_t)bh*SS + (size_t)c*CH)*DH;
    const __half* kvp = g_pkvh + ((size_t)bh*NC + c)*DH*DH;
    const float*  ksp = g_pks  + ((size_t)bh*NC + c)*DH;

    for (int idx = tid; idx < 2048; idx += 256) {
        int r = idx >> 5, c2 = idx & 31;
        *(__half2*)&sQ[r*TPH + 2*c2]   = *(const __half2*)(qp  + r*DH + 2*c2);
        *(__half2*)&sK[r*TPH + 2*c2]   = *(const __half2*)(kp  + r*DH + 2*c2);
        *(__half2*)&sKVT[r*TPH + 2*c2] = *(const __half2*)(kvp + r*DH + 2*c2);
        __half2 v2 = *(const __half2*)(vp + r*DH + 2*c2);
        sVT[(2*c2+0)*TPH + r] = __low2half(v2);
        sVT[(2*c2+1)*TPH + r] = __high2half(v2);
    }
    if (tid < DH) sKs[tid] = ksp[tid];
    __syncthreads();

    const uint32_t aoff = (uint32_t)((lane & 15) * TPHB + (lane >> 4) * 16);
    const uint32_t boff = (uint32_t)((lane & 7) * TPHB + ((lane >> 3) & 1) * 16);
    const uint32_t awm = (uint32_t)(wm * 32 * TPHB);
    const uint32_t bwn = (uint32_t)(wn * 16 * TPHB);
    const int rl = lane >> 2, cl = (lane & 3) * 2;

    // ---- mma1: S = q . k^T ----
    {
        const uint32_t abase = smem_u32(sQ) + awm + aoff;
        const uint32_t bbase = smem_u32(sK) + bwn + boff;
        float acc[2][2][4] = {};
#pragma unroll
        for (int kk = 0; kk < 4; kk++) {
            uint32_t afr[2][4], bfr[2][2];
#pragma unroll
            for (int mf = 0; mf < 2; mf++)
                ldsm_x4(afr[mf][0], afr[mf][1], afr[mf][2], afr[mf][3],
                        abase + (uint32_t)(mf * 16 * TPHB) + kk * 32);
#pragma unroll
            for (int nf = 0; nf < 2; nf++)
                ldsm_x2(bfr[nf][0], bfr[nf][1],
                        bbase + (uint32_t)(nf * 8 * TPHB) + kk * 32);
#pragma unroll
            for (int mf = 0; mf < 2; mf++)
#pragma unroll
                for (int nf = 0; nf < 2; nf++)
                    mma_f16(acc[mf][nf][0], acc[mf][nf][1],
                            acc[mf][nf][2], acc[mf][nf][3],
                            afr[mf][0], afr[mf][1], afr[mf][2], afr[mf][3],
                            bfr[nf][0], bfr[nf][1]);
        }
#pragma unroll
        for (int mf = 0; mf < 2; mf++)
#pragma unroll
            for (int nf = 0; nf < 2; nf++)
#pragma unroll
                for (int half = 0; half < 2; half++) {
                    int t = wm*32 + mf*16 + rl + half*8;
                    int s = wn*16 + nf*8 + cl;
                    float v0 = (s   <= t) ? acc[mf][nf][half*2]   : 0.f;
                    float v1 = (s+1 <= t) ? acc[mf][nf][half*2+1] : 0.f;
                    *(__half2*)&sS[t*TPH + s] = __floats2half2_rn(v0, v1);
                }
    }
    __syncthreads();

    // den (fp32, from fp16-rounded S for num/den consistency)
    if (tid < DH) {
        float d = 0.f;
#pragma unroll 8
        for (int s = 0; s < CH; s++) d += __half2float(sS[tid*TPH + s]);
#pragma unroll 8
        for (int e = 0; e < DH; e++)
            d += __half2float(sQ[tid*TPH + e]) * sKs[e];
        sDen[tid] = d;
    }

    // ---- mma2+3: ctx = S @ v + q @ KV_pre ----
    float acc[2][2][4] = {};
    {
        const uint32_t a1 = smem_u32(sS) + awm + aoff;
        const uint32_t b1 = smem_u32(sVT) + bwn + boff;
#pragma unroll
        for (int kk = 0; kk < 4; kk++) {
            uint32_t afr[2][4], bfr[2][2];
#pragma unroll
            for (int mf = 0; mf < 2; mf++)
                ldsm_x4(afr[mf][0], afr[mf][1], afr[mf][2], afr[mf][3],
                        a1 + (uint32_t)(mf * 16 * TPHB) + kk * 32);
#pragma unroll
            for (int nf = 0; nf < 2; nf++)
                ldsm_x2(bfr[nf][0], bfr[nf][1],
                        b1 + (uint32_t)(nf * 8 * TPHB) + kk * 32);
#pragma unroll
            for (int mf = 0; mf < 2; mf++)
#pragma unroll
                for (int nf = 0; nf < 2; nf++)
                    mma_f16(acc[mf][nf][0], acc[mf][nf][1],
                            acc[mf][nf][2], acc[mf][nf][3],
                            afr[mf][0], afr[mf][1], afr[mf][2], afr[mf][3],
                            bfr[nf][0], bfr[nf][1]);
        }
        const uint32_t a2 = smem_u32(sQ) + awm + aoff;
        const uint32_t b2 = smem_u32(sKVT) + bwn + boff;
#pragma unroll
        for (int kk = 0; kk < 4; kk++) {
            uint32_t afr[2][4], bfr[2][2];
#pragma unroll
            for (int mf = 0; mf < 2; mf++)
                ldsm_x4(afr[mf][0], afr[mf][1], afr[mf][2], afr[mf][3],
                        a2 + (uint32_t)(mf * 16 * TPHB) + kk * 32);
#pragma unroll
            for (int nf = 0; nf < 2; nf++)
                ldsm_x2(bfr[nf][0], bfr[nf][1],
                        b2 + (uint32_t)(nf * 8 * TPHB) + kk * 32);
#pragma unroll
            for (int mf = 0; mf < 2; mf++)
#pragma unroll
                for (int nf = 0; nf < 2; nf++)
                    mma_f16(acc[mf][nf][0], acc[mf][nf][1],
                            acc[mf][nf][2], acc[mf][nf][3],
                            afr[mf][0], afr[mf][1], afr[mf][2], afr[mf][3],
                            bfr[nf][0], bfr[nf][1]);
        }
    }
    __syncthreads();   // sDen visibility

    const int b_ = bh >> 3, h = bh & 7;
#pragma unroll
    for (int mf = 0; mf < 2; mf++)
#pragma unroll
        for (int nf = 0; nf < 2; nf++)
#pragma unroll
            for (int half = 0; half < 2; half++) {
                int t = wm*32 + mf*16 + rl + half*8;
                int d = wn*16 + nf*8 + cl;
                float inv = 1.f / sDen[t];
                int sg = c*CH + t;
                *(__half2*)(g_ctxh + ((size_t)(b_*SS + sg))*DM + h*DH + d) =
                    __floats2half2_rn(acc[mf][nf][half*2]   * inv,
                                      acc[mf][nf][half*2+1] * inv);
            }
}

// ---------------------------------------------------------------------------
extern "C" void kernel_launch(void* const* d_in, const int* in_sizes, int n_in,
                              void* d_out, int out_size)
{
    const float* x   = (const float*)d_in[0];
    const float* Wqk = (const float*)d_in[1];
    const float* bqk = (const float*)d_in[2];
    const float* Wv  = (const float*)d_in[3];
    const float* bv  = (const float*)d_in[4];
    const float* Wo  = (const float*)d_in[5];
    const float* bo  = (const float*)d_in[6];
    float* out = (float*)d_out;

    cudaFuncSetAttribute(gemm_f16<0>,
        cudaFuncAttributeMaxDynamicSharedMemorySize, GEMM_SMEM_BYTES);
    cudaFuncSetAttribute(gemm_f16<1>,
        cudaFuncAttributeMaxDynamicSharedMemorySize, GEMM_SMEM_BYTES);

    round_kernel<<<592, 256>>>(x, Wqk, Wv, Wo);
    gemm_f16<0><<<dim3(24, 32), 128, GEMM_SMEM_BYTES>>>(bqk, bv, nullptr);
    chunkkv_kernel<<<dim3(NC, BH), 256>>>();
    scan_kernel<<<dim3(BH, 8), 256>>>();
    ctx_kernel<<<dim3(NC, BH), 256>>>();
    gemm_f16<1><<<dim3(8, 32), 128, GEMM_SMEM_BYTES>>>(bo, nullptr, out);
}

// round 13
// speedup vs baseline: 1.2659x; 1.2659x over previous
#include <cuda_runtime.h>
#include <cuda_fp16.h>
#include <math.h>
#include <stdint.h>

// Problem constants
#define BB 2
#define SS 2048
#define DM 512
#define HH 8
#define DH 64
#define CH 64               // chunk length
#define NC (SS/CH)          // 32 chunks
#define BH (BB*HH)          // 16 (b,h) pairs

// Scratch (device globals)
__device__ __half g_qh  [BH*SS*DH];     // elu+1, fp16
__device__ __half g_kh  [BH*SS*DH];
__device__ __half g_vh  [BH*SS*DH];
__device__ __half g_ckvh[BH*NC*DH*DH];  // per-chunk (V^T K): [d][e]
__device__ float  g_cks [BH*NC*DH];
__device__ __half g_pkvh[BH*NC*DH*DH];  // exclusive prefix (still [d][e])
__device__ float  g_pks [BH*NC*DH];
__device__ __half g_ctxh[BB*SS*DM];     // context fp16
__device__ __half g_xh  [BB*SS*DM];     // x fp16
__device__ __half g_wh  [3*DM*DM];      // [Wqk ; Wv] fp16
__device__ __half g_woh [DM*DM];        // Wo fp16

// ===========================================================================
// helpers
// ===========================================================================
__device__ __forceinline__ uint32_t smem_u32(const void* p) {
    uint32_t a;
    asm("{ .reg .u64 t; cvta.to.shared.u64 t, %1; cvt.u32.u64 %0, t; }"
        : "=r"(a) : "l"(p));
    return a;
}
__device__ __forceinline__ void ldsm_x4(uint32_t& r0, uint32_t& r1,
                                        uint32_t& r2, uint32_t& r3, uint32_t a) {
    asm volatile("ldmatrix.sync.aligned.m8n8.x4.shared.b16 {%0,%1,%2,%3}, [%4];"
                 : "=r"(r0), "=r"(r1), "=r"(r2), "=r"(r3) : "r"(a));
}
__device__ __forceinline__ void ldsm_x2(uint32_t& r0, uint32_t& r1, uint32_t a) {
    asm volatile("ldmatrix.sync.aligned.m8n8.x2.shared.b16 {%0,%1}, [%2];"
                 : "=r"(r0), "=r"(r1) : "r"(a));
}
__device__ __forceinline__ void mma_f16(float& c0, float& c1, float& c2, float& c3,
                                        uint32_t a0, uint32_t a1, uint32_t a2, uint32_t a3,
                                        uint32_t b0, uint32_t b1) {
    asm volatile("mma.sync.aligned.m16n8k16.row.col.f32.f16.f16.f32 "
                 "{%0,%1,%2,%3}, {%4,%5,%6,%7}, {%8,%9}, {%0,%1,%2,%3};"
                 : "+f"(c0), "+f"(c1), "+f"(c2), "+f"(c3)
                 : "r"(a0), "r"(a1), "r"(a2), "r"(a3), "r"(b0), "r"(b1));
}
#define CP16(dst, src) \
    asm volatile("cp.async.cg.shared.global [%0], [%1], 16;" \
                 :: "r"(dst), "l"(src) : "memory")
#define CP_COMMIT() asm volatile("cp.async.commit_group;" ::: "memory")
#define CP_WAIT1()  asm volatile("cp.async.wait_group 1;" ::: "memory")

// ===========================================================================
// Kernel 0: convert inputs to fp16.
// ===========================================================================
__global__ __launch_bounds__(256) void round_kernel(
    const float* __restrict__ x, const float* __restrict__ Wqk,
    const float* __restrict__ Wv, const float* __restrict__ Wo)
{
    const int tid = blockIdx.x * 256 + threadIdx.x;
    const int stride = gridDim.x * 256;
    const float2* x2 = (const float2*)x;
    __half2* xo = (__half2*)g_xh;
    for (int i = tid; i < BB*SS*DM/2; i += stride) xo[i] = __float22half2_rn(x2[i]);
    const float2* a2 = (const float2*)Wqk;
    __half2* ao = (__half2*)g_wh;
    for (int i = tid; i < 2*DM*DM/2; i += stride) ao[i] = __float22half2_rn(a2[i]);
    const float2* b2 = (const float2*)Wv;
    __half2* bo = (__half2*)(g_wh + 2*DM*DM);
    for (int i = tid; i < DM*DM/2; i += stride) bo[i] = __float22half2_rn(b2[i]);
    const float2* c2 = (const float2*)Wo;
    __half2* co = (__half2*)g_woh;
    for (int i = tid; i < DM*DM/2; i += stride) co[i] = __float22half2_rn(c2[i]);
}

// ===========================================================================
// fp16 mma.sync GEMM, cp.async 3-stage pipeline.
// C[128x128] = A[128xK] * B[128xK]^T (NT), K=512, BK=32 halves.
// 256 threads = 8 warps (2M x 4N), warp tile 64x32, frags m16n8k16.
// smem rows: 32 halves + 8 pad = 80 B. 3 stages = 60 KB -> occ 3,
// proj grid 384 CTAs fits one wave (444 slots).
// MODE 0: proj (A=g_xh, B=g_wh, bias+elu, scatter q/k/v fp16)
// MODE 1: out  (A=g_ctxh, B=g_woh, bias, store fp32 out)
// ===========================================================================
#define BKH 32
#define ROWB 80
#define TILEBH (128*ROWB)                  // 10240
#define STAGEBH (2*TILEBH)                 // 20480
#define NST 3
#define GEMM_SMEM_BYTES (NST*STAGEBH)      // 61440

template<int MODE>
__global__ __launch_bounds__(256, 3) void gemm_f16(
    const float* __restrict__ bias0, const float* __restrict__ bias1,
    float* __restrict__ outp)
{
    extern __shared__ __align__(16) char smem[];
    const int tid = threadIdx.x;
    const int wid = tid >> 5, lane = tid & 31;
    const int wm = wid & 1, wn = wid >> 1;
    const int jt = blockIdx.x * 128;
    const int nt = blockIdx.y * 128;

    const __half* Ap = (MODE == 1) ? (const __half*)g_ctxh : (const __half*)g_xh;
    const __half* Bp = (MODE == 1) ? (const __half*)g_woh  : (const __half*)g_wh;

    const uint32_t sb = smem_u32(smem);

    // per-thread gmem rows + smem dst (2 x 16B for A, 2 for B per K-tile)
    const __half* rowA[2]; const __half* rowB[2]; uint32_t dA[2], dB[2];
#pragma unroll
    for (int u = 0; u < 2; u++) {
        int idx = tid + u * 256;            // 0..511
        int r = idx >> 2, c = idx & 3;      // row 0..127, 16B chunk 0..3
        dA[u] = (uint32_t)(r * ROWB + c * 16);
        dB[u] = dA[u] + TILEBH;
        rowA[u] = Ap + (size_t)(nt + r) * DM + c * 8;
        rowB[u] = Bp + (size_t)(jt + r) * DM + c * 8;
    }

    // ldmatrix lane offsets
    const uint32_t aoff = (uint32_t)((lane & 15) * ROWB + (lane >> 4) * 16
                                     + wm * 64 * ROWB);
    const uint32_t boff = (uint32_t)((lane & 7) * ROWB + ((lane >> 3) & 1) * 16
                                     + wn * 32 * ROWB) + TILEBH;

    float acc[4][4][4] = {};

    // prologue: stages 0,1
#pragma unroll
    for (int s = 0; s < 2; s++) {
        const uint32_t st = sb + s * STAGEBH;
        const int k0 = s * BKH;
#pragma unroll
        for (int u = 0; u < 2; u++) {
            CP16(st + dA[u], rowA[u] + k0);
            CP16(st + dB[u], rowB[u] + k0);
        }
        CP_COMMIT();
    }

    for (int it = 0; it < 16; it++) {
        const int buf = it % NST;
        CP_WAIT1();
        __syncthreads();
        const uint32_t abase = sb + buf * STAGEBH + aoff;
        const uint32_t bbase = sb + buf * STAGEBH + boff;
#pragma unroll
        for (int kk = 0; kk < 2; kk++) {
            uint32_t afr[4][4], bfr[4][2];
#pragma unroll
            for (int mf = 0; mf < 4; mf++)
                ldsm_x4(afr[mf][0], afr[mf][1], afr[mf][2], afr[mf][3],
                        abase + (uint32_t)(mf * 16 * ROWB) + kk * 32);
#pragma unroll
            for (int nf = 0; nf < 4; nf++)
                ldsm_x2(bfr[nf][0], bfr[nf][1],
                        bbase + (uint32_t)(nf * 8 * ROWB) + kk * 32);
#pragma unroll
            for (int mf = 0; mf < 4; mf++)
#pragma unroll
                for (int nf = 0; nf < 4; nf++)
                    mma_f16(acc[mf][nf][0], acc[mf][nf][1],
                            acc[mf][nf][2], acc[mf][nf][3],
                            afr[mf][0], afr[mf][1], afr[mf][2], afr[mf][3],
                            bfr[nf][0], bfr[nf][1]);
        }
        __syncthreads();
        const int nxt = it + 2;
        if (nxt < 16) {
            const uint32_t st = sb + (nxt % NST) * STAGEBH;
            const int k0 = nxt * BKH;
#pragma unroll
            for (int u = 0; u < 2; u++) {
                CP16(st + dA[u], rowA[u] + k0);
                CP16(st + dB[u], rowB[u] + k0);
            }
        }
        CP_COMMIT();
    }

    const int rl = lane >> 2, cl = (lane & 3) * 2;
#pragma unroll
    for (int mf = 0; mf < 4; mf++) {
#pragma unroll
        for (int nf = 0; nf < 4; nf++) {
            const int j0 = jt + wn * 32 + nf * 8 + cl;
#pragma unroll
            for (int half = 0; half < 2; half++) {
                const int row = nt + wm * 64 + mf * 16 + rl + half * 8;
                float v0 = acc[mf][nf][half * 2 + 0];
                float v1 = acc[mf][nf][half * 2 + 1];
                if (MODE == 0) {
                    const int b_ = row >> 11, s_ = row & (SS - 1);
                    if (j0 < 2 * DM) {
                        v0 += bias0[j0]; v1 += bias0[j0 + 1];
                        v0 = (v0 > 0.f) ? v0 + 1.f : expf(v0);
                        v1 = (v1 > 0.f) ? v1 + 1.f : expf(v1);
                        int jm = j0 & (DM - 1);
                        int h = jm >> 6, d = jm & 63;
                        __half* dst = (j0 < DM ? g_qh : g_kh)
                                    + (((size_t)(b_ * HH + h) * SS + s_) * DH + d);
                        *(__half2*)dst = __floats2half2_rn(v0, v1);
                    } else {
                        int jm = j0 - 2 * DM;
                        v0 += bias1[jm]; v1 += bias1[jm + 1];
                        int h = jm >> 6, d = jm & 63;
                        __half* dst = g_vh + (((size_t)(b_ * HH + h) * SS + s_) * DH + d);
                        *(__half2*)dst = __floats2half2_rn(v0, v1);
                    }
                } else {
                    float2 bi = *(const float2*)(bias0 + j0);
                    *(float2*)(outp + (size_t)row * DM + j0) =
                        make_float2(v0 + bi.x, v1 + bi.y);
                }
            }
        }
    }
}

// ===========================================================================
// Kernel 2: per-chunk M[d][e] = sum_s v[s][d] k[s][e]  (A=v^T, B=k^T), fp16.
// 128 threads = 4 warps (2x2), warp tile 32x32, K=s=64 -> 4 k16 steps.
// Tile rows: 64 halves + 8 pad = 144 B.
// ===========================================================================
#define TPH 72
#define TPHB 144

__global__ __launch_bounds__(128) void chunkkv_kernel()
{
    __shared__ __half sKT[64*TPH];
    __shared__ __half sVT[64*TPH];
    const int c  = blockIdx.x, bh = blockIdx.y;
    const int tid = threadIdx.x;
    const int wid = tid >> 5, lane = tid & 31;
    const int wm = wid & 1, wn = wid >> 1;
    const __half* kp = g_kh + ((size_t)bh*SS + (size_t)c*CH)*DH;
    const __half* vp = g_vh + ((size_t)bh*SS + (size_t)c*CH)*DH;

    for (int idx = tid; idx < 2048; idx += 128) {
        int r = idx >> 5, c2 = idx & 31;
        __half2 k2 = *(const __half2*)(kp + r*DH + 2*c2);
        sKT[(2*c2+0)*TPH + r] = __low2half(k2);
        sKT[(2*c2+1)*TPH + r] = __high2half(k2);
        __half2 v2 = *(const __half2*)(vp + r*DH + 2*c2);
        sVT[(2*c2+0)*TPH + r] = __low2half(v2);
        sVT[(2*c2+1)*TPH + r] = __high2half(v2);
    }
    __syncthreads();

    const uint32_t aoff = (uint32_t)((lane & 15) * TPHB + (lane >> 4) * 16);
    const uint32_t boff = (uint32_t)((lane & 7) * TPHB + ((lane >> 3) & 1) * 16);
    const uint32_t abase = smem_u32(sVT) + (uint32_t)(wm * 32 * TPHB) + aoff;
    const uint32_t bbase = smem_u32(sKT) + (uint32_t)(wn * 32 * TPHB) + boff;

    float acc[2][4][4] = {};
#pragma unroll
    for (int kk = 0; kk < 4; kk++) {
        uint32_t afr[2][4], bfr[4][2];
#pragma unroll
        for (int mf = 0; mf < 2; mf++)
            ldsm_x4(afr[mf][0], afr[mf][1], afr[mf][2], afr[mf][3],
                    abase + (uint32_t)(mf * 16 * TPHB) + kk * 32);
#pragma unroll
        for (int nf = 0; nf < 4; nf++)
            ldsm_x2(bfr[nf][0], bfr[nf][1],
                    bbase + (uint32_t)(nf * 8 * TPHB) + kk * 32);
#pragma unroll
        for (int mf = 0; mf < 2; mf++)
#pragma unroll
            for (int nf = 0; nf < 4; nf++)
                mma_f16(acc[mf][nf][0], acc[mf][nf][1],
                        acc[mf][nf][2], acc[mf][nf][3],
                        afr[mf][0], afr[mf][1], afr[mf][2], afr[mf][3],
                        bfr[nf][0], bfr[nf][1]);
    }

    __half* dst = g_ckvh + ((size_t)bh*NC + c)*DH*DH;
    const int rl = lane >> 2, cl = (lane & 3) * 2;
#pragma unroll
    for (int mf = 0; mf < 2; mf++)
#pragma unroll
        for (int nf = 0; nf < 4; nf++)
#pragma unroll
            for (int half = 0; half < 2; half++) {
                int row = wm*32 + mf*16 + rl + half*8;   // d
                int col = wn*32 + nf*8 + cl;             // e
                *(__half2*)(dst + row*DH + col) =
                    __floats2half2_rn(acc[mf][nf][half*2], acc[mf][nf][half*2+1]);
            }

    if (tid < DH) {
        float s = 0.f;
#pragma unroll 8
        for (int r = 0; r < CH; r++) s += __half2float(sKT[tid*TPH + r]);
        g_cks[((size_t)bh*NC + c)*DH + tid] = s;
    }
}

// ===========================================================================
// Kernel 3: exclusive prefix scan (fp32 accumulate, fp16 storage).
// ===========================================================================
__global__ __launch_bounds__(256) void scan_kernel()
{
    const int bh = blockIdx.x;
    const int tid = threadIdx.x;
    const int e = blockIdx.y * 256 + tid;       // 0..4095
    const size_t base = (size_t)bh * NC;
    __half v[NC];
#pragma unroll
    for (int c = 0; c < NC; c++)
        v[c] = g_ckvh[(base + c) * (DH*DH) + e];
    float run = 0.f;
#pragma unroll
    for (int c = 0; c < NC; c++) {
        g_pkvh[(base + c) * (DH*DH) + e] = __float2half_rn(run);
        run += __half2float(v[c]);
    }
    if (blockIdx.y == 0 && tid < DH) {
        float w[NC];
#pragma unroll
        for (int c = 0; c < NC; c++) w[c] = g_cks[(base + c)*DH + tid];
        float r = 0.f;
#pragma unroll
        for (int c = 0; c < NC; c++) {
            g_pks[(base + c)*DH + tid] = r;
            r += w[c];
        }
    }
}

// ===========================================================================
// Kernel 4: per-chunk context, fp16 mma.
//  S = q k^T (mask) ; den = rowsum(S_h) + q.ks_pre
//  ctx = (S_h @ v + q @ KV_pre) / den
// ===========================================================================
__global__ __launch_bounds__(128) void ctx_kernel()
{
    __shared__ __half sQ  [64*TPH];   // [t][e]
    __shared__ __half sK  [64*TPH];   // [s][e]
    __shared__ __half sS  [64*TPH];   // [t][s] masked fp16
    __shared__ __half sVT [64*TPH];   // [d][s]
    __shared__ __half sKVT[64*TPH];   // [d][e]
    __shared__ float  sKs [64];
    __shared__ float  sDen[64];

    const int c  = blockIdx.x, bh = blockIdx.y;
    const int tid = threadIdx.x;
    const int wid = tid >> 5, lane = tid & 31;
    const int wm = wid & 1, wn = wid >> 1;

    const __half* qp  = g_qh   + ((size_t)bh*SS + (size_t)c*CH)*DH;
    const __half* kp  = g_kh   + ((size_t)bh*SS + (size_t)c*CH)*DH;
    const __half* vp  = g_vh   + ((size_t)bh*SS + (size_t)c*CH)*DH;
    const __half* kvp = g_pkvh + ((size_t)bh*NC + c)*DH*DH;
    const float*  ksp = g_pks  + ((size_t)bh*NC + c)*DH;

    for (int idx = tid; idx < 2048; idx += 128) {
        int r = idx >> 5, c2 = idx & 31;
        *(__half2*)&sQ[r*TPH + 2*c2]   = *(const __half2*)(qp  + r*DH + 2*c2);
        *(__half2*)&sK[r*TPH + 2*c2]   = *(const __half2*)(kp  + r*DH + 2*c2);
        *(__half2*)&sKVT[r*TPH + 2*c2] = *(const __half2*)(kvp + r*DH + 2*c2);
        __half2 v2 = *(const __half2*)(vp + r*DH + 2*c2);
        sVT[(2*c2+0)*TPH + r] = __low2half(v2);
        sVT[(2*c2+1)*TPH + r] = __high2half(v2);
    }
    if (tid < DH) sKs[tid] = ksp[tid];
    __syncthreads();

    const uint32_t aoff = (uint32_t)((lane & 15) * TPHB + (lane >> 4) * 16);
    const uint32_t boff = (uint32_t)((lane & 7) * TPHB + ((lane >> 3) & 1) * 16);
    const uint32_t awm = (uint32_t)(wm * 32 * TPHB);
    const uint32_t bwn = (uint32_t)(wn * 32 * TPHB);
    const int rl = lane >> 2, cl = (lane & 3) * 2;

    // ---- mma1: S = q . k^T ----
    {
        const uint32_t abase = smem_u32(sQ) + awm + aoff;
        const uint32_t bbase = smem_u32(sK) + bwn + boff;
        float acc[2][4][4] = {};
#pragma unroll
        for (int kk = 0; kk < 4; kk++) {
            uint32_t afr[2][4], bfr[4][2];
#pragma unroll
            for (int mf = 0; mf < 2; mf++)
                ldsm_x4(afr[mf][0], afr[mf][1], afr[mf][2], afr[mf][3],
                        abase + (uint32_t)(mf * 16 * TPHB) + kk * 32);
#pragma unroll
            for (int nf = 0; nf < 4; nf++)
                ldsm_x2(bfr[nf][0], bfr[nf][1],
                        bbase + (uint32_t)(nf * 8 * TPHB) + kk * 32);
#pragma unroll
            for (int mf = 0; mf < 2; mf++)
#pragma unroll
                for (int nf = 0; nf < 4; nf++)
                    mma_f16(acc[mf][nf][0], acc[mf][nf][1],
                            acc[mf][nf][2], acc[mf][nf][3],
                            afr[mf][0], afr[mf][1], afr[mf][2], afr[mf][3],
                            bfr[nf][0], bfr[nf][1]);
        }
#pragma unroll
        for (int mf = 0; mf < 2; mf++)
#pragma unroll
            for (int nf = 0; nf < 4; nf++)
#pragma unroll
                for (int half = 0; half < 2; half++) {
                    int t = wm*32 + mf*16 + rl + half*8;
                    int s = wn*32 + nf*8 + cl;
                    float v0 = (s   <= t) ? acc[mf][nf][half*2]   : 0.f;
                    float v1 = (s+1 <= t) ? acc[mf][nf][half*2+1] : 0.f;
                    *(__half2*)&sS[t*TPH + s] = __floats2half2_rn(v0, v1);
                }
    }
    __syncthreads();

    // den (fp32, from fp16-rounded S for num/den consistency)
    if (tid < DH) {
        float d = 0.f;
#pragma unroll 8
        for (int s = 0; s < CH; s++) d += __half2float(sS[tid*TPH + s]);
#pragma unroll 8
        for (int e = 0; e < DH; e++)
            d += __half2float(sQ[tid*TPH + e]) * sKs[e];
        sDen[tid] = d;
    }

    // ---- mma2+3: ctx = S @ v + q @ KV_pre ----
    float acc[2][4][4] = {};
    {
        const uint32_t a1 = smem_u32(sS) + awm + aoff;
        const uint32_t b1 = smem_u32(sVT) + bwn + boff;
#pragma unroll
        for (int kk = 0; kk < 4; kk++) {
            uint32_t afr[2][4], bfr[4][2];
#pragma unroll
            for (int mf = 0; mf < 2; mf++)
                ldsm_x4(afr[mf][0], afr[mf][1], afr[mf][2], afr[mf][3],
                        a1 + (uint32_t)(mf * 16 * TPHB) + kk * 32);
#pragma unroll
            for (int nf = 0; nf < 4; nf++)
                ldsm_x2(bfr[nf][0], bfr[nf][1],
                        b1 + (uint32_t)(nf * 8 * TPHB) + kk * 32);
#pragma unroll
            for (int mf = 0; mf < 2; mf++)
#pragma unroll
                for (int nf = 0; nf < 4; nf++)
                    mma_f16(acc[mf][nf][0], acc[mf][nf][1],
                            acc[mf][nf][2], acc[mf][nf][3],
                            afr[mf][0], afr[mf][1], afr[mf][2], afr[mf][3],
                            bfr[nf][0], bfr[nf][1]);
        }
        const uint32_t a2 = smem_u32(sQ) + awm + aoff;
        const uint32_t b2 = smem_u32(sKVT) + bwn + boff;
#pragma unroll
        for (int kk = 0; kk < 4; kk++) {
            uint32_t afr[2][4], bfr[4][2];
#pragma unroll
            for (int mf = 0; mf < 2; mf++)
                ldsm_x4(afr[mf][0], afr[mf][1], afr[mf][2], afr[mf][3],
                        a2 + (uint32_t)(mf * 16 * TPHB) + kk * 32);
#pragma unroll
            for (int nf = 0; nf < 4; nf++)
                ldsm_x2(bfr[nf][0], bfr[nf][1],
                        b2 + (uint32_t)(nf * 8 * TPHB) + kk * 32);
#pragma unroll
            for (int mf = 0; mf < 2; mf++)
#pragma unroll
                for (int nf = 0; nf < 4; nf++)
                    mma_f16(acc[mf][nf][0], acc[mf][nf][1],
                            acc[mf][nf][2], acc[mf][nf][3],
                            afr[mf][0], afr[mf][1], afr[mf][2], afr[mf][3],
                            bfr[nf][0], bfr[nf][1]);
        }
    }
    __syncthreads();   // sDen visibility

    const int b_ = bh >> 3, h = bh & 7;
#pragma unroll
    for (int mf = 0; mf < 2; mf++)
#pragma unroll
        for (int nf = 0; nf < 4; nf++)
#pragma unroll
            for (int half = 0; half < 2; half++) {
                int t = wm*32 + mf*16 + rl + half*8;
                int d = wn*32 + nf*8 + cl;
                float inv = 1.f / sDen[t];
                int sg = c*CH + t;
                *(__half2*)(g_ctxh + ((size_t)(b_*SS + sg))*DM + h*DH + d) =
                    __floats2half2_rn(acc[mf][nf][half*2]   * inv,
                                      acc[mf][nf][half*2+1] * inv);
            }
}

// ---------------------------------------------------------------------------
extern "C" void kernel_launch(void* const* d_in, const int* in_sizes, int n_in,
                              void* d_out, int out_size)
{
    const float* x   = (const float*)d_in[0];
    const float* Wqk = (const float*)d_in[1];
    const float* bqk = (const float*)d_in[2];
    const float* Wv  = (const float*)d_in[3];
    const float* bv  = (const float*)d_in[4];
    const float* Wo  = (const float*)d_in[5];
    const float* bo  = (const float*)d_in[6];
    float* out = (float*)d_out;

    cudaFuncSetAttribute(gemm_f16<0>,
        cudaFuncAttributeMaxDynamicSharedMemorySize, GEMM_SMEM_BYTES);
    cudaFuncSetAttribute(gemm_f16<1>,
        cudaFuncAttributeMaxDynamicSharedMemorySize, GEMM_SMEM_BYTES);

    round_kernel<<<592, 256>>>(x, Wqk, Wv, Wo);
    gemm_f16<0><<<dim3(12, 32), 256, GEMM_SMEM_BYTES>>>(bqk, bv, nullptr);
    chunkkv_kernel<<<dim3(NC, BH), 128>>>();
    scan_kernel<<<dim3(BH, 16), 256>>>();
    ctx_kernel<<<dim3(NC, BH), 128>>>();
    gemm_f16<1><<<dim3(4, 32), 256, GEMM_SMEM_BYTES>>>(bo, nullptr, out);
}

// round 16
// speedup vs baseline: 1.4912x; 1.1780x over previous
#include <cuda_runtime.h>
#include <cuda_fp16.h>
#include <math.h>
#include <stdint.h>

// Problem constants
#define BB 2
#define SS 2048
#define DM 512
#define HH 8
#define DH 64
#define CH 64               // chunk length
#define NC (SS/CH)          // 32 chunks
#define BH (BB*HH)          // 16 (b,h) pairs

// Scratch (device globals)
__device__ __half g_qh  [BH*SS*DH];     // elu+1, fp16
__device__ __half g_kh  [BH*SS*DH];
__device__ __half g_vh  [BH*SS*DH];
__device__ __half g_ckvh[BH*NC*DH*DH];  // per-chunk (V^T K): [d][e]
__device__ float  g_cks [BH*NC*DH];
__device__ __half g_pkvh[BH*NC*DH*DH];  // exclusive prefix (still [d][e])
__device__ float  g_pks [BH*NC*DH];
__device__ __half g_ctxh[BB*SS*DM];     // context fp16
__device__ __half g_xh  [BB*SS*DM];     // x fp16
__device__ __half g_wh  [3*DM*DM];      // [Wqk ; Wv] fp16
__device__ __half g_woh [DM*DM];        // Wo fp16

// ===========================================================================
// helpers
// ===========================================================================
__device__ __forceinline__ uint32_t smem_u32(const void* p) {
    uint32_t a;
    asm("{ .reg .u64 t; cvta.to.shared.u64 t, %1; cvt.u32.u64 %0, t; }"
        : "=r"(a) : "l"(p));
    return a;
}
__device__ __forceinline__ void ldsm_x4(uint32_t& r0, uint32_t& r1,
                                        uint32_t& r2, uint32_t& r3, uint32_t a) {
    asm volatile("ldmatrix.sync.aligned.m8n8.x4.shared.b16 {%0,%1,%2,%3}, [%4];"
                 : "=r"(r0), "=r"(r1), "=r"(r2), "=r"(r3) : "r"(a));
}
__device__ __forceinline__ void ldsm_x2(uint32_t& r0, uint32_t& r1, uint32_t a) {
    asm volatile("ldmatrix.sync.aligned.m8n8.x2.shared.b16 {%0,%1}, [%2];"
                 : "=r"(r0), "=r"(r1) : "r"(a));
}
__device__ __forceinline__ void mma_f16(float& c0, float& c1, float& c2, float& c3,
                                        uint32_t a0, uint32_t a1, uint32_t a2, uint32_t a3,
                                        uint32_t b0, uint32_t b1) {
    asm volatile("mma.sync.aligned.m16n8k16.row.col.f32.f16.f16.f32 "
                 "{%0,%1,%2,%3}, {%4,%5,%6,%7}, {%8,%9}, {%0,%1,%2,%3};"
                 : "+f"(c0), "+f"(c1), "+f"(c2), "+f"(c3)
                 : "r"(a0), "r"(a1), "r"(a2), "r"(a3), "r"(b0), "r"(b1));
}
#define CP16(dst, src) \
    asm volatile("cp.async.cg.shared.global [%0], [%1], 16;" \
                 :: "r"(dst), "l"(src) : "memory")
#define CP_COMMIT() asm volatile("cp.async.commit_group;" ::: "memory")
#define CP_WAIT2()  asm volatile("cp.async.wait_group 2;" ::: "memory")

// ===========================================================================
// Kernel 0: convert inputs to fp16.
// ===========================================================================
__global__ __launch_bounds__(256) void round_kernel(
    const float* __restrict__ x, const float* __restrict__ Wqk,
    const float* __restrict__ Wv, const float* __restrict__ Wo)
{
    const int tid = blockIdx.x * 256 + threadIdx.x;
    const int stride = gridDim.x * 256;
    const float2* x2 = (const float2*)x;
    __half2* xo = (__half2*)g_xh;
    for (int i = tid; i < BB*SS*DM/2; i += stride) xo[i] = __float22half2_rn(x2[i]);
    const float2* a2 = (const float2*)Wqk;
    __half2* ao = (__half2*)g_wh;
    for (int i = tid; i < 2*DM*DM/2; i += stride) ao[i] = __float22half2_rn(a2[i]);
    const float2* b2 = (const float2*)Wv;
    __half2* bo = (__half2*)(g_wh + 2*DM*DM);
    for (int i = tid; i < DM*DM/2; i += stride) bo[i] = __float22half2_rn(b2[i]);
    const float2* c2 = (const float2*)Wo;
    __half2* co = (__half2*)g_woh;
    for (int i = tid; i < DM*DM/2; i += stride) co[i] = __float22half2_rn(c2[i]);
}

// ===========================================================================
// fp16 mma.sync GEMM, cp.async 4-stage pipeline.
// Tile: 64(M) x 128(N), K=512, BK=32 halves. 256 threads = 8 warps (2M x 4N),
// warp tile 32x32, frags m16n8k16. smem row = 32 halves + 8 pad = 80 B.
// stage = (64+128)*80 = 15360 B; 4 stages = 60 KB.
// acc = 32 regs/thread -> no spill, occ 2-3 (ptxas-chosen).
// proj grid 768 CTAs -> better makespan quantization than 384 big tiles.
// MODE 0: proj (A=g_xh, B=g_wh, bias+elu, scatter q/k/v fp16)
// MODE 1: out  (A=g_ctxh, B=g_woh, bias, store fp32 out)
// ===========================================================================
#define BKH 32
#define ROWB 80
#define TILEA (64*ROWB)                    // 5120
#define TILEBB (128*ROWB)                  // 10240
#define STAGEBH (TILEA+TILEBB)             // 15360
#define NST 4
#define GEMM_SMEM_BYTES (NST*STAGEBH)      // 61440

template<int MODE>
__global__ __launch_bounds__(256) void gemm_f16(
    const float* __restrict__ bias0, const float* __restrict__ bias1,
    float* __restrict__ outp)
{
    extern __shared__ __align__(16) char smem[];
    const int tid = threadIdx.x;
    const int wid = tid >> 5, lane = tid & 31;
    const int wm = wid & 1, wn = wid >> 1;          // 2(M) x 4(N) warps
    const int jt = blockIdx.x * 128;
    const int nt = blockIdx.y * 64;

    const __half* Ap = (MODE == 1) ? (const __half*)g_ctxh : (const __half*)g_xh;
    const __half* Bp = (MODE == 1) ? (const __half*)g_woh  : (const __half*)g_wh;

    const uint32_t sb = smem_u32(smem);

    // per-stage loads: A 256 x 16B chunks (1/thread), B 512 chunks (2/thread)
    const __half* rowA; uint32_t dA;
    const __half* rowB[2]; uint32_t dB[2];
    {
        int r = tid >> 2, c = tid & 3;              // A: row 0..63, chunk 0..3
        dA = (uint32_t)(r * ROWB + c * 16);
        rowA = Ap + (size_t)(nt + r) * DM + c * 8;
    }
#pragma unroll
    for (int u = 0; u < 2; u++) {
        int idx = tid + u * 256;                    // 0..511
        int r = idx >> 2, c = idx & 3;              // B: row 0..127
        dB[u] = (uint32_t)(TILEA + r * ROWB + c * 16);
        rowB[u] = Bp + (size_t)(jt + r) * DM + c * 8;
    }

    // ldmatrix lane offsets
    const uint32_t aoff = (uint32_t)((lane & 15) * ROWB + (lane >> 4) * 16
                                     + wm * 32 * ROWB);
    const uint32_t boff = (uint32_t)((lane & 7) * ROWB + ((lane >> 3) & 1) * 16
                                     + wn * 32 * ROWB) + TILEA;

    float acc[2][4][4] = {};

    // prologue: stages 0..2
#pragma unroll
    for (int s = 0; s < 3; s++) {
        const uint32_t st = sb + s * STAGEBH;
        const int k0 = s * BKH;
        CP16(st + dA, rowA + k0);
#pragma unroll
        for (int u = 0; u < 2; u++) CP16(st + dB[u], rowB[u] + k0);
        CP_COMMIT();
    }

    for (int it = 0; it < 16; it++) {
        const int buf = it & 3;
        CP_WAIT2();
        __syncthreads();
        const uint32_t abase = sb + buf * STAGEBH + aoff;
        const uint32_t bbase = sb + buf * STAGEBH + boff;
#pragma unroll
        for (int kk = 0; kk < 2; kk++) {
            uint32_t afr[2][4], bfr[4][2];
#pragma unroll
            for (int mf = 0; mf < 2; mf++)
                ldsm_x4(afr[mf][0], afr[mf][1], afr[mf][2], afr[mf][3],
                        abase + (uint32_t)(mf * 16 * ROWB) + kk * 32);
#pragma unroll
            for (int nf = 0; nf < 4; nf++)
                ldsm_x2(bfr[nf][0], bfr[nf][1],
                        bbase + (uint32_t)(nf * 8 * ROWB) + kk * 32);
#pragma unroll
            for (int mf = 0; mf < 2; mf++)
#pragma unroll
                for (int nf = 0; nf < 4; nf++)
                    mma_f16(acc[mf][nf][0], acc[mf][nf][1],
                            acc[mf][nf][2], acc[mf][nf][3],
                            afr[mf][0], afr[mf][1], afr[mf][2], afr[mf][3],
                            bfr[nf][0], bfr[nf][1]);
        }
        __syncthreads();
        const int nxt = it + 3;
        if (nxt < 16) {
            const uint32_t st = sb + (nxt & 3) * STAGEBH;
            const int k0 = nxt * BKH;
            CP16(st + dA, rowA + k0);
#pragma unroll
            for (int u = 0; u < 2; u++) CP16(st + dB[u], rowB[u] + k0);
        }
        CP_COMMIT();
    }

    const int rl = lane >> 2, cl = (lane & 3) * 2;
#pragma unroll
    for (int mf = 0; mf < 2; mf++) {
#pragma unroll
        for (int nf = 0; nf < 4; nf++) {
            const int j0 = jt + wn * 32 + nf * 8 + cl;
#pragma unroll
            for (int half = 0; half < 2; half++) {
                const int row = nt + wm * 32 + mf * 16 + rl + half * 8;
                float v0 = acc[mf][nf][half * 2 + 0];
                float v1 = acc[mf][nf][half * 2 + 1];
                if (MODE == 0) {
                    const int b_ = row >> 11, s_ = row & (SS - 1);
                    if (j0 < 2 * DM) {
                        v0 += bias0[j0]; v1 += bias0[j0 + 1];
                        v0 = (v0 > 0.f) ? v0 + 1.f : expf(v0);
                        v1 = (v1 > 0.f) ? v1 + 1.f : expf(v1);
                        int jm = j0 & (DM - 1);
                        int h = jm >> 6, d = jm & 63;
                        __half* dst = (j0 < DM ? g_qh : g_kh)
                                    + (((size_t)(b_ * HH + h) * SS + s_) * DH + d);
                        *(__half2*)dst = __floats2half2_rn(v0, v1);
                    } else {
                        int jm = j0 - 2 * DM;
                        v0 += bias1[jm]; v1 += bias1[jm + 1];
                        int h = jm >> 6, d = jm & 63;
                        __half* dst = g_vh + (((size_t)(b_ * HH + h) * SS + s_) * DH + d);
                        *(__half2*)dst = __floats2half2_rn(v0, v1);
                    }
                } else {
                    float2 bi = *(const float2*)(bias0 + j0);
                    *(float2*)(outp + (size_t)row * DM + j0) =
                        make_float2(v0 + bi.x, v1 + bi.y);
                }
            }
        }
    }
}

// ===========================================================================
// Kernel 2: per-chunk M[d][e] = sum_s v[s][d] k[s][e]  (A=v^T, B=k^T), fp16.
// 128 threads = 4 warps (2x2), warp tile 32x32, K=s=64 -> 4 k16 steps.
// Tile rows: 64 halves + 8 pad = 144 B.
// ===========================================================================
#define TPH 72
#define TPHB 144

__global__ __launch_bounds__(128) void chunkkv_kernel()
{
    __shared__ __half sKT[64*TPH];
    __shared__ __half sVT[64*TPH];
    const int c  = blockIdx.x, bh = blockIdx.y;
    const int tid = threadIdx.x;
    const int wid = tid >> 5, lane = tid & 31;
    const int wm = wid & 1, wn = wid >> 1;
    const __half* kp = g_kh + ((size_t)bh*SS + (size_t)c*CH)*DH;
    const __half* vp = g_vh + ((size_t)bh*SS + (size_t)c*CH)*DH;

    for (int idx = tid; idx < 2048; idx += 128) {
        int r = idx >> 5, c2 = idx & 31;
        __half2 k2 = *(const __half2*)(kp + r*DH + 2*c2);
        sKT[(2*c2+0)*TPH + r] = __low2half(k2);
        sKT[(2*c2+1)*TPH + r] = __high2half(k2);
        __half2 v2 = *(const __half2*)(vp + r*DH + 2*c2);
        sVT[(2*c2+0)*TPH + r] = __low2half(v2);
        sVT[(2*c2+1)*TPH + r] = __high2half(v2);
    }
    __syncthreads();

    const uint32_t aoff = (uint32_t)((lane & 15) * TPHB + (lane >> 4) * 16);
    const uint32_t boff = (uint32_t)((lane & 7) * TPHB + ((lane >> 3) & 1) * 16);
    const uint32_t abase = smem_u32(sVT) + (uint32_t)(wm * 32 * TPHB) + aoff;
    const uint32_t bbase = smem_u32(sKT) + (uint32_t)(wn * 32 * TPHB) + boff;

    float acc[2][4][4] = {};
#pragma unroll
    for (int kk = 0; kk < 4; kk++) {
        uint32_t afr[2][4], bfr[4][2];
#pragma unroll
        for (int mf = 0; mf < 2; mf++)
            ldsm_x4(afr[mf][0], afr[mf][1], afr[mf][2], afr[mf][3],
                    abase + (uint32_t)(mf * 16 * TPHB) + kk * 32);
#pragma unroll
        for (int nf = 0; nf < 4; nf++)
            ldsm_x2(bfr[nf][0], bfr[nf][1],
                    bbase + (uint32_t)(nf * 8 * TPHB) + kk * 32);
#pragma unroll
        for (int mf = 0; mf < 2; mf++)
#pragma unroll
            for (int nf = 0; nf < 4; nf++)
                mma_f16(acc[mf][nf][0], acc[mf][nf][1],
                        acc[mf][nf][2], acc[mf][nf][3],
                        afr[mf][0], afr[mf][1], afr[mf][2], afr[mf][3],
                        bfr[nf][0], bfr[nf][1]);
    }

    __half* dst = g_ckvh + ((size_t)bh*NC + c)*DH*DH;
    const int rl = lane >> 2, cl = (lane & 3) * 2;
#pragma unroll
    for (int mf = 0; mf < 2; mf++)
#pragma unroll
        for (int nf = 0; nf < 4; nf++)
#pragma unroll
            for (int half = 0; half < 2; half++) {
                int row = wm*32 + mf*16 + rl + half*8;   // d
                int col = wn*32 + nf*8 + cl;             // e
                *(__half2*)(dst + row*DH + col) =
                    __floats2half2_rn(acc[mf][nf][half*2], acc[mf][nf][half*2+1]);
            }

    if (tid < DH) {
        float s = 0.f;
#pragma unroll 8
        for (int r = 0; r < CH; r++) s += __half2float(sKT[tid*TPH + r]);
        g_cks[((size_t)bh*NC + c)*DH + tid] = s;
    }
}

// ===========================================================================
// Kernel 3: exclusive prefix scan (fp32 accumulate, fp16 storage).
// ===========================================================================
__global__ __launch_bounds__(256) void scan_kernel()
{
    const int bh = blockIdx.x;
    const int tid = threadIdx.x;
    const int e = blockIdx.y * 256 + tid;       // 0..4095
    const size_t base = (size_t)bh * NC;
    __half v[NC];
#pragma unroll
    for (int c = 0; c < NC; c++)
        v[c] = g_ckvh[(base + c) * (DH*DH) + e];
    float run = 0.f;
#pragma unroll
    for (int c = 0; c < NC; c++) {
        g_pkvh[(base + c) * (DH*DH) + e] = __float2half_rn(run);
        run += __half2float(v[c]);
    }
    if (blockIdx.y == 0 && tid < DH) {
        float w[NC];
#pragma unroll
        for (int c = 0; c < NC; c++) w[c] = g_cks[(base + c)*DH + tid];
        float r = 0.f;
#pragma unroll
        for (int c = 0; c < NC; c++) {
            g_pks[(base + c)*DH + tid] = r;
            r += w[c];
        }
    }
}

// ===========================================================================
// Kernel 4: per-chunk context, fp16 mma.
//  S = q k^T (mask) ; den = rowsum(S_h) + q.ks_pre
//  ctx = (S_h @ v + q @ KV_pre) / den
// ===========================================================================
__global__ __launch_bounds__(128) void ctx_kernel()
{
    __shared__ __half sQ  [64*TPH];   // [t][e]
    __shared__ __half sK  [64*TPH];   // [s][e]
    __shared__ __half sS  [64*TPH];   // [t][s] masked fp16
    __shared__ __half sVT [64*TPH];   // [d][s]
    __shared__ __half sKVT[64*TPH];   // [d][e]
    __shared__ float  sKs [64];
    __shared__ float  sDen[64];

    const int c  = blockIdx.x, bh = blockIdx.y;
    const int tid = threadIdx.x;
    const int wid = tid >> 5, lane = tid & 31;
    const int wm = wid & 1, wn = wid >> 1;

    const __half* qp  = g_qh   + ((size_t)bh*SS + (size_t)c*CH)*DH;
    const __half* kp  = g_kh   + ((size_t)bh*SS + (size_t)c*CH)*DH;
    const __half* vp  = g_vh   + ((size_t)bh*SS + (size_t)c*CH)*DH;
    const __half* kvp = g_pkvh + ((size_t)bh*NC + c)*DH*DH;
    const float*  ksp = g_pks  + ((size_t)bh*NC + c)*DH;

    for (int idx = tid; idx < 2048; idx += 128) {
        int r = idx >> 5, c2 = idx & 31;
        *(__half2*)&sQ[r*TPH + 2*c2]   = *(const __half2*)(qp  + r*DH + 2*c2);
        *(__half2*)&sK[r*TPH + 2*c2]   = *(const __half2*)(kp  + r*DH + 2*c2);
        *(__half2*)&sKVT[r*TPH + 2*c2] = *(const __half2*)(kvp + r*DH + 2*c2);
        __half2 v2 = *(const __half2*)(vp + r*DH + 2*c2);
        sVT[(2*c2+0)*TPH + r] = __low2half(v2);
        sVT[(2*c2+1)*TPH + r] = __high2half(v2);
    }
    if (tid < DH) sKs[tid] = ksp[tid];
    __syncthreads();

    const uint32_t aoff = (uint32_t)((lane & 15) * TPHB + (lane >> 4) * 16);
    const uint32_t boff = (uint32_t)((lane & 7) * TPHB + ((lane >> 3) & 1) * 16);
    const uint32_t awm = (uint32_t)(wm * 32 * TPHB);
    const uint32_t bwn = (uint32_t)(wn * 32 * TPHB);
    const int rl = lane >> 2, cl = (lane & 3) * 2;

    // ---- mma1: S = q . k^T ----
    {
        const uint32_t abase = smem_u32(sQ) + awm + aoff;
        const uint32_t bbase = smem_u32(sK) + bwn + boff;
        float acc[2][4][4] = {};
#pragma unroll
        for (int kk = 0; kk < 4; kk++) {
            uint32_t afr[2][4], bfr[4][2];
#pragma unroll
            for (int mf = 0; mf < 2; mf++)
                ldsm_x4(afr[mf][0], afr[mf][1], afr[mf][2], afr[mf][3],
                        abase + (uint32_t)(mf * 16 * TPHB) + kk * 32);
#pragma unroll
            for (int nf = 0; nf < 4; nf++)
                ldsm_x2(bfr[nf][0], bfr[nf][1],
                        bbase + (uint32_t)(nf * 8 * TPHB) + kk * 32);
#pragma unroll
            for (int mf = 0; mf < 2; mf++)
#pragma unroll
                for (int nf = 0; nf < 4; nf++)
                    mma_f16(acc[mf][nf][0], acc[mf][nf][1],
                            acc[mf][nf][2], acc[mf][nf][3],
                            afr[mf][0], afr[mf][1], afr[mf][2], afr[mf][3],
                            bfr[nf][0], bfr[nf][1]);
        }
#pragma unroll
        for (int mf = 0; mf < 2; mf++)
#pragma unroll
            for (int nf = 0; nf < 4; nf++)
#pragma unroll
                for (int half = 0; half < 2; half++) {
                    int t = wm*32 + mf*16 + rl + half*8;
                    int s = wn*32 + nf*8 + cl;
                    float v0 = (s   <= t) ? acc[mf][nf][half*2]   : 0.f;
                    float v1 = (s+1 <= t) ? acc[mf][nf][half*2+1] : 0.f;
                    *(__half2*)&sS[t*TPH + s] = __floats2half2_rn(v0, v1);
                }
    }
    __syncthreads();

    // den (fp32, from fp16-rounded S for num/den consistency)
    if (tid < DH) {
        float d = 0.f;
#pragma unroll 8
        for (int s = 0; s < CH; s++) d += __half2float(sS[tid*TPH + s]);
#pragma unroll 8
        for (int e = 0; e < DH; e++)
            d += __half2float(sQ[tid*TPH + e]) * sKs[e];
        sDen[tid] = d;
    }

    // ---- mma2+3: ctx = S @ v + q @ KV_pre ----
    float acc[2][4][4] = {};
    {
        const uint32_t a1 = smem_u32(sS) + awm + aoff;
        const uint32_t b1 = smem_u32(sVT) + bwn + boff;
#pragma unroll
        for (int kk = 0; kk < 4; kk++) {
            uint32_t afr[2][4], bfr[4][2];
#pragma unroll
            for (int mf = 0; mf < 2; mf++)
                ldsm_x4(afr[mf][0], afr[mf][1], afr[mf][2], afr[mf][3],
                        a1 + (uint32_t)(mf * 16 * TPHB) + kk * 32);
#pragma unroll
            for (int nf = 0; nf < 4; nf++)
                ldsm_x2(bfr[nf][0], bfr[nf][1],
                        b1 + (uint32_t)(nf * 8 * TPHB) + kk * 32);
#pragma unroll
            for (int mf = 0; mf < 2; mf++)
#pragma unroll
                for (int nf = 0; nf < 4; nf++)
                    mma_f16(acc[mf][nf][0], acc[mf][nf][1],
                            acc[mf][nf][2], acc[mf][nf][3],
                            afr[mf][0], afr[mf][1], afr[mf][2], afr[mf][3],
                            bfr[nf][0], bfr[nf][1]);
        }
        const uint32_t a2 = smem_u32(sQ) + awm + aoff;
        const uint32_t b2 = smem_u32(sKVT) + bwn + boff;
#pragma unroll
        for (int kk = 0; kk < 4; kk++) {
            uint32_t afr[2][4], bfr[4][2];
#pragma unroll
            for (int mf = 0; mf < 2; mf++)
                ldsm_x4(afr[mf][0], afr[mf][1], afr[mf][2], afr[mf][3],
                        a2 + (uint32_t)(mf * 16 * TPHB) + kk * 32);
#pragma unroll
            for (int nf = 0; nf < 4; nf++)
                ldsm_x2(bfr[nf][0], bfr[nf][1],
                        b2 + (uint32_t)(nf * 8 * TPHB) + kk * 32);
#pragma unroll
            for (int mf = 0; mf < 2; mf++)
#pragma unroll
                for (int nf = 0; nf < 4; nf++)
                    mma_f16(acc[mf][nf][0], acc[mf][nf][1],
                            acc[mf][nf][2], acc[mf][nf][3],
                            afr[mf][0], afr[mf][1], afr[mf][2], afr[mf][3],
                            bfr[nf][0], bfr[nf][1]);
        }
    }
    __syncthreads();   // sDen visibility

    const int b_ = bh >> 3, h = bh & 7;
#pragma unroll
    for (int mf = 0; mf < 2; mf++)
#pragma unroll
        for (int nf = 0; nf < 4; nf++)
#pragma unroll
            for (int half = 0; half < 2; half++) {
                int t = wm*32 + mf*16 + rl + half*8;
                int d = wn*32 + nf*8 + cl;
                float inv = 1.f / sDen[t];
                int sg = c*CH + t;
                *(__half2*)(g_ctxh + ((size_t)(b_*SS + sg))*DM + h*DH + d) =
                    __floats2half2_rn(acc[mf][nf][half*2]   * inv,
                                      acc[mf][nf][half*2+1] * inv);
            }
}

// ---------------------------------------------------------------------------
extern "C" void kernel_launch(void* const* d_in, const int* in_sizes, int n_in,
                              void* d_out, int out_size)
{
    const float* x   = (const float*)d_in[0];
    const float* Wqk = (const float*)d_in[1];
    const float* bqk = (const float*)d_in[2];
    const float* Wv  = (const float*)d_in[3];
    const float* bv  = (const float*)d_in[4];
    const float* Wo  = (const float*)d_in[5];
    const float* bo  = (const float*)d_in[6];
    float* out = (float*)d_out;

    cudaFuncSetAttribute(gemm_f16<0>,
        cudaFuncAttributeMaxDynamicSharedMemorySize, GEMM_SMEM_BYTES);
    cudaFuncSetAttribute(gemm_f16<1>,
        cudaFuncAttributeMaxDynamicSharedMemorySize, GEMM_SMEM_BYTES);

    round_kernel<<<592, 256>>>(x, Wqk, Wv, Wo);
    gemm_f16<0><<<dim3(12, 64), 256, GEMM_SMEM_BYTES>>>(bqk, bv, nullptr);
    chunkkv_kernel<<<dim3(NC, BH), 128>>>();
    scan_kernel<<<dim3(BH, 16), 256>>>();
    ctx_kernel<<<dim3(NC, BH), 128>>>();
    gemm_f16<1><<<dim3(4, 64), 256, GEMM_SMEM_BYTES>>>(bo, nullptr, out);
}